// round 13
// baseline (speedup 1.0000x reference)
#include <cuda_runtime.h>
#include <cuda_fp16.h>
#include <cstdint>

#define K_DIM 4096
#define N_DIM 4096
#define M_DIM 8192

#define BM 128
#define BN 128
#define BK 32
#define PADH 8
#define NTILES (K_DIM / BK)

// Dequantized weights [N][K], K contiguous, k PERMUTED within 8-blocks
// (order 0,4,1,5,2,6,3,7). g_X uses the same permutation -> dot products equal.
__device__ __half g_W[(size_t)N_DIM * K_DIM];
__device__ __half g_X[(size_t)M_DIM * K_DIM];

__device__ __forceinline__ void ldmx4(uint32_t* r, uint32_t addr) {
    asm volatile("ldmatrix.sync.aligned.m8n8.x4.shared.b16 {%0,%1,%2,%3}, [%4];"
                 : "=r"(r[0]), "=r"(r[1]), "=r"(r[2]), "=r"(r[3]) : "r"(addr));
}
__device__ __forceinline__ void mma16816(float* c, const uint32_t* a, uint32_t b0, uint32_t b1) {
    asm volatile(
        "mma.sync.aligned.m16n8k16.row.col.f32.f16.f16.f32 "
        "{%0,%1,%2,%3}, {%4,%5,%6,%7}, {%8,%9}, {%0,%1,%2,%3};"
        : "+f"(c[0]), "+f"(c[1]), "+f"(c[2]), "+f"(c[3])
        : "r"(a[0]), "r"(a[1]), "r"(a[2]), "r"(a[3]), "r"(b0), "r"(b1));
}

// ---------------- Kernel 0: x fp32 -> fp16, k-permuted within 8-blocks ----------------
__global__ __launch_bounds__(256) void convert_x_kernel(const float* __restrict__ xf) {
    size_t i = ((size_t)blockIdx.x * blockDim.x + threadIdx.x) * 8;
    float4 v0 = *reinterpret_cast<const float4*>(xf + i);
    float4 v1 = *reinterpret_cast<const float4*>(xf + i + 4);
    __half h[8];
    // permuted order: x0,x4,x1,x5,x2,x6,x3,x7
    h[0] = __float2half_rn(v0.x); h[1] = __float2half_rn(v1.x);
    h[2] = __float2half_rn(v0.y); h[3] = __float2half_rn(v1.y);
    h[4] = __float2half_rn(v0.z); h[5] = __float2half_rn(v1.z);
    h[6] = __float2half_rn(v0.w); h[7] = __float2half_rn(v1.w);
    *reinterpret_cast<uint4*>(&g_X[i]) = *reinterpret_cast<const uint4*>(h);
}

// ---------------- Kernel 1: GPTQ dequant (LOP3 magic, permuted stores) ----------------
__global__ __launch_bounds__(256) void dequant_kernel(const int* __restrict__ qw,
                                                      const float* __restrict__ scales,
                                                      const int* __restrict__ qz) {
    int gw = blockIdx.x * 8 + (threadIdx.x >> 5);   // 0..4095
    int lane = threadIdx.x & 31;
    int n = (gw & 127) * 32 + lane;
    int g = gw >> 7;                                // 0..31
    __half s = __float2half_rn(scales[g * N_DIM + n]);
    __half2 s2 = __half2half2(s);
    int z = ((qz[g * (N_DIM / 8) + (n >> 3)] >> ((n & 7) * 4)) & 0xF) + 1;
    __half2 mz = __half2half2(__float2half_rn(1024.0f + (float)z));
    const int r0 = g * 16;
#pragma unroll
    for (int i = 0; i < 16; i++) {
        int w = qw[(size_t)(r0 + i) * N_DIM + n];
        uint32_t out[4];
#pragma unroll
        for (int j = 0; j < 4; j++) {
            uint32_t t = (((uint32_t)w >> (4 * j)) & 0x000F000Fu) | 0x64006400u;
            __half2 hv = __hmul2(__hsub2(*reinterpret_cast<__half2*>(&t), mz), s2);
            out[j] = *reinterpret_cast<uint32_t*>(&hv);
        }
        *reinterpret_cast<uint4*>(&g_W[(size_t)n * K_DIM + (r0 + i) * 8]) =
            *reinterpret_cast<const uint4*>(out);
    }
}

// ---------------- Kernel 2: GEMM (R2 skeleton + x4 B-loads + 2x unrolled loop) ----------------
__global__ __launch_bounds__(256) void gemm_kernel(const float* __restrict__ biasf,
                                                   float* __restrict__ out) {
    __shared__ __half As[2][BM][BK + PADH];
    __shared__ __half Bs[2][BN][BK + PADH];

    const int tid = threadIdx.x;
    const int lane = tid & 31;
    const int warp = tid >> 5;
    const int warpM = warp & 1;   // 0..1
    const int warpN = warp >> 1;  // 0..3
    const int bm = blockIdx.y * BM;
    const int bn = blockIdx.x * BN;

    float c[4][4][4];
#pragma unroll
    for (int i = 0; i < 4; i++)
#pragma unroll
        for (int j = 0; j < 4; j++)
#pragma unroll
            for (int e = 0; e < 4; e++) c[i][j][e] = 0.0f;

    auto load_stage = [&](int s, int kt) {
#pragma unroll
        for (int i = 0; i < 2; i++) {
            int id = tid + i * 256;      // 512 16B vectors per operand per stage
            int row = id >> 2;           // 0..127
            int c8 = (id & 3) * 8;       // 0,8,16,24 halves
            const __half* srcA = g_X + (size_t)(bm + row) * K_DIM + kt * BK + c8;
            uint32_t dA = (uint32_t)__cvta_generic_to_shared(&As[s][row][c8]);
            asm volatile("cp.async.cg.shared.global [%0], [%1], 16;" :: "r"(dA), "l"(srcA));
            const __half* srcB = g_W + (size_t)(bn + row) * K_DIM + kt * BK + c8;
            uint32_t dB = (uint32_t)__cvta_generic_to_shared(&Bs[s][row][c8]);
            asm volatile("cp.async.cg.shared.global [%0], [%1], 16;" :: "r"(dB), "l"(srcB));
        }
        asm volatile("cp.async.commit_group;");
    };

    // A fragment rows: lanes 0-15 pick m-row, lanes>=16 pick +8B k offset.
    const int am0 = warpM * 64 + (lane & 15);
    const int akoff = ((lane >> 4) << 3);
    // B x4: 16 rows (two fn blocks) x both k-halves in one ldmatrix.
    const int bn0 = warpN * 32 + (lane & 15);
    const int bkoff = ((lane >> 4) << 3);

    auto compute = [&](int cur) {
#pragma unroll
        for (int kk = 0; kk < BK; kk += 16) {
            uint32_t a[4][4];
#pragma unroll
            for (int fm = 0; fm < 4; fm++) {
                uint32_t addr = (uint32_t)__cvta_generic_to_shared(
                    &As[cur][am0 + fm * 16][kk + akoff]);
                ldmx4(a[fm], addr);
            }
            uint32_t b[4][2];
#pragma unroll
            for (int h = 0; h < 2; h++) {
                uint32_t r[4];
                uint32_t addr = (uint32_t)__cvta_generic_to_shared(
                    &Bs[cur][bn0 + h * 16][kk + bkoff]);
                ldmx4(r, addr);
                // matrix0: rows 0-7,k0-7 ; matrix1: rows 8-15,k0-7
                // matrix2: rows 0-7,k8-15; matrix3: rows 8-15,k8-15
                b[h * 2][0]     = r[0]; b[h * 2][1]     = r[2];
                b[h * 2 + 1][0] = r[1]; b[h * 2 + 1][1] = r[3];
            }
#pragma unroll
            for (int fm = 0; fm < 4; fm++)
#pragma unroll
                for (int fn = 0; fn < 4; fn++)
                    mma16816(c[fm][fn], a[fm], b[fn][0], b[fn][1]);
        }
    };

    load_stage(0, 0);

#pragma unroll 2
    for (int kt = 0; kt < NTILES; kt++) {
        const int cur = kt & 1;
        asm volatile("cp.async.wait_group 0;");
        __syncthreads();
        if (kt + 1 < NTILES) load_stage(cur ^ 1, kt + 1);
        compute(cur);
    }

    // Epilogue: fp16(sum) + fp16(bias) in fp16, store f32 (reference rounding).
    const int row_in = lane >> 2;         // 0..7
    const int col_in = (lane & 3) * 2;    // 0,2,4,6
#pragma unroll
    for (int fn = 0; fn < 4; fn++) {
        int n = bn + warpN * 32 + fn * 8 + col_in;
        __half bh0 = __float2half_rn(biasf[n]);
        __half bh1 = __float2half_rn(biasf[n + 1]);
#pragma unroll
        for (int fm = 0; fm < 4; fm++) {
            int m = bm + warpM * 64 + fm * 16 + row_in;
            float2 v0, v1;
            v0.x = __half2float(__hadd(__float2half_rn(c[fm][fn][0]), bh0));
            v0.y = __half2float(__hadd(__float2half_rn(c[fm][fn][1]), bh1));
            v1.x = __half2float(__hadd(__float2half_rn(c[fm][fn][2]), bh0));
            v1.y = __half2float(__hadd(__float2half_rn(c[fm][fn][3]), bh1));
            *reinterpret_cast<float2*>(&out[(size_t)m * N_DIM + n]) = v0;
            *reinterpret_cast<float2*>(&out[(size_t)(m + 8) * N_DIM + n]) = v1;
        }
    }
}

extern "C" void kernel_launch(void* const* d_in, const int* in_sizes, int n_in,
                              void* d_out, int out_size) {
    const float* x       = (const float*)d_in[0];
    const int*   qweight = (const int*)d_in[1];
    const float* scales  = (const float*)d_in[2];
    const int*   qzeros  = (const int*)d_in[3];
    // d_in[4] = g_idx: k/128, folded into dequant indexing
    const float* bias    = (const float*)d_in[5];
    float* out = (float*)d_out;

    convert_x_kernel<<<((size_t)M_DIM * K_DIM) / (256 * 8), 256>>>(x);
    dequant_kernel<<<512, 256>>>(qweight, scales, qzeros);

    dim3 grid(N_DIM / BN, M_DIM / BM);
    gemm_kernel<<<grid, 256>>>(bias, out);
}

// round 14
// speedup vs baseline: 1.0337x; 1.0337x over previous
#include <cuda_runtime.h>
#include <cuda_fp16.h>
#include <cstdint>

#define K_DIM 4096
#define N_DIM 4096
#define M_DIM 8192

#define BM 128
#define BN 128
#define BK 32
#define PADH 8
#define NST 3
#define NTILES (K_DIM / BK)

// Dequantized weights [N][K], K contiguous, k PERMUTED within 8-blocks
// (order 0,4,1,5,2,6,3,7). g_X uses the same permutation -> dot products equal.
__device__ __half g_W[(size_t)N_DIM * K_DIM];
__device__ __half g_X[(size_t)M_DIM * K_DIM];

// ---------------- Kernel 0: x fp32 -> fp16, k-permuted within 8-blocks ----------------
__global__ __launch_bounds__(256) void convert_x_kernel(const float* __restrict__ xf) {
    size_t i = ((size_t)blockIdx.x * blockDim.x + threadIdx.x) * 8;
    float4 v0 = *reinterpret_cast<const float4*>(xf + i);
    float4 v1 = *reinterpret_cast<const float4*>(xf + i + 4);
    __half h[8];
    // permuted order: x0,x4,x1,x5,x2,x6,x3,x7
    h[0] = __float2half_rn(v0.x); h[1] = __float2half_rn(v1.x);
    h[2] = __float2half_rn(v0.y); h[3] = __float2half_rn(v1.y);
    h[4] = __float2half_rn(v0.z); h[5] = __float2half_rn(v1.z);
    h[6] = __float2half_rn(v0.w); h[7] = __float2half_rn(v1.w);
    *reinterpret_cast<uint4*>(&g_X[i]) = *reinterpret_cast<const uint4*>(h);
}

// ---------------- Kernel 1: GPTQ dequant (LOP3 magic, permuted stores) ----------------
__global__ __launch_bounds__(256) void dequant_kernel(const int* __restrict__ qw,
                                                      const float* __restrict__ scales,
                                                      const int* __restrict__ qz) {
    int gw = blockIdx.x * 8 + (threadIdx.x >> 5);   // 0..4095
    int lane = threadIdx.x & 31;
    int n = (gw & 127) * 32 + lane;
    int g = gw >> 7;                                // 0..31
    __half s = __float2half_rn(scales[g * N_DIM + n]);
    __half2 s2 = __half2half2(s);
    int z = ((qz[g * (N_DIM / 8) + (n >> 3)] >> ((n & 7) * 4)) & 0xF) + 1;
    __half2 mz = __half2half2(__float2half_rn(1024.0f + (float)z));
    const int r0 = g * 16;
#pragma unroll
    for (int i = 0; i < 16; i++) {
        int w = qw[(size_t)(r0 + i) * N_DIM + n];
        uint32_t out[4];
#pragma unroll
        for (int j = 0; j < 4; j++) {
            uint32_t t = (((uint32_t)w >> (4 * j)) & 0x000F000Fu) | 0x64006400u;
            __half2 hv = __hmul2(__hsub2(*reinterpret_cast<__half2*>(&t), mz), s2);
            out[j] = *reinterpret_cast<uint32_t*>(&hv);
        }
        *reinterpret_cast<uint4*>(&g_W[(size_t)n * K_DIM + (r0 + i) * 8]) =
            *reinterpret_cast<const uint4*>(out);
    }
}

// ---------------- Kernel 2: GEMM (R2/R12 config, 3-stage variant) ----------------
// 128x128x32 CTA tile, 8 warps 2(M)x4(N), warp tile 64x32, x2 B-loads.
// 3-stage cp.async with wait_group 1: each stage load gets 2 compute periods.
__global__ __launch_bounds__(256) void gemm_kernel(const float* __restrict__ biasf,
                                                   float* __restrict__ out) {
    __shared__ __half As[NST][BM][BK + PADH];
    __shared__ __half Bs[NST][BN][BK + PADH];

    const int tid = threadIdx.x;
    const int lane = tid & 31;
    const int warp = tid >> 5;
    const int warpM = warp & 1;   // 0..1
    const int warpN = warp >> 1;  // 0..3
    const int bm = blockIdx.y * BM;
    const int bn = blockIdx.x * BN;

    float c[4][4][4];
#pragma unroll
    for (int i = 0; i < 4; i++)
#pragma unroll
        for (int j = 0; j < 4; j++)
#pragma unroll
            for (int e = 0; e < 4; e++) c[i][j][e] = 0.0f;

    auto load_stage = [&](int s, int kt) {
#pragma unroll
        for (int i = 0; i < 2; i++) {
            int id = tid + i * 256;      // 512 16B vectors per operand per stage
            int row = id >> 2;           // 0..127
            int c8 = (id & 3) * 8;       // 0,8,16,24 halves
            const __half* srcA = g_X + (size_t)(bm + row) * K_DIM + kt * BK + c8;
            uint32_t dA = (uint32_t)__cvta_generic_to_shared(&As[s][row][c8]);
            asm volatile("cp.async.cg.shared.global [%0], [%1], 16;" :: "r"(dA), "l"(srcA));
            const __half* srcB = g_W + (size_t)(bn + row) * K_DIM + kt * BK + c8;
            uint32_t dB = (uint32_t)__cvta_generic_to_shared(&Bs[s][row][c8]);
            asm volatile("cp.async.cg.shared.global [%0], [%1], 16;" :: "r"(dB), "l"(srcB));
        }
        asm volatile("cp.async.commit_group;");
    };

    load_stage(0, 0);
    load_stage(1, 1);

#pragma unroll 1
    for (int kt = 0; kt < NTILES; kt++) {
        const int cur = kt % NST;
        asm volatile("cp.async.wait_group 1;");   // group kt complete (kt+1 may pend)
        __syncthreads();
        if (kt + 2 < NTILES) load_stage((kt + 2) % NST, kt + 2);  // stage (kt-1)%3

#pragma unroll
        for (int kk = 0; kk < BK; kk += 16) {
            uint32_t a[4][4];
#pragma unroll
            for (int fm = 0; fm < 4; fm++) {
                int m0 = warpM * 64 + fm * 16 + (lane & 15);
                uint32_t addr = (uint32_t)__cvta_generic_to_shared(
                    &As[cur][m0][kk + ((lane >> 4) << 3)]);
                asm volatile("ldmatrix.sync.aligned.m8n8.x4.shared.b16 {%0,%1,%2,%3}, [%4];"
                             : "=r"(a[fm][0]), "=r"(a[fm][1]), "=r"(a[fm][2]), "=r"(a[fm][3])
                             : "r"(addr));
            }
            uint32_t b[4][2];
#pragma unroll
            for (int fn = 0; fn < 4; fn++) {
                int n0 = warpN * 32 + fn * 8 + (lane & 7);
                uint32_t addr = (uint32_t)__cvta_generic_to_shared(
                    &Bs[cur][n0][kk + ((lane >> 3) & 1) * 8]);
                asm volatile("ldmatrix.sync.aligned.m8n8.x2.shared.b16 {%0,%1}, [%2];"
                             : "=r"(b[fn][0]), "=r"(b[fn][1])
                             : "r"(addr));
            }
#pragma unroll
            for (int fm = 0; fm < 4; fm++)
#pragma unroll
                for (int fn = 0; fn < 4; fn++) {
                    asm volatile(
                        "mma.sync.aligned.m16n8k16.row.col.f32.f16.f16.f32 "
                        "{%0,%1,%2,%3}, {%4,%5,%6,%7}, {%8,%9}, {%0,%1,%2,%3};"
                        : "+f"(c[fm][fn][0]), "+f"(c[fm][fn][1]),
                          "+f"(c[fm][fn][2]), "+f"(c[fm][fn][3])
                        : "r"(a[fm][0]), "r"(a[fm][1]), "r"(a[fm][2]), "r"(a[fm][3]),
                          "r"(b[fn][0]), "r"(b[fn][1]));
                }
        }
    }

    // Epilogue: fp16(sum) + fp16(bias) in fp16, store f32 (reference rounding).
    const int row_in = lane >> 2;         // 0..7
    const int col_in = (lane & 3) * 2;    // 0,2,4,6
#pragma unroll
    for (int fn = 0; fn < 4; fn++) {
        int n = bn + warpN * 32 + fn * 8 + col_in;
        __half bh0 = __float2half_rn(biasf[n]);
        __half bh1 = __float2half_rn(biasf[n + 1]);
#pragma unroll
        for (int fm = 0; fm < 4; fm++) {
            int m = bm + warpM * 64 + fm * 16 + row_in;
            float2 v0, v1;
            v0.x = __half2float(__hadd(__float2half_rn(c[fm][fn][0]), bh0));
            v0.y = __half2float(__hadd(__float2half_rn(c[fm][fn][1]), bh1));
            v1.x = __half2float(__hadd(__float2half_rn(c[fm][fn][2]), bh0));
            v1.y = __half2float(__hadd(__float2half_rn(c[fm][fn][3]), bh1));
            *reinterpret_cast<float2*>(&out[(size_t)m * N_DIM + n]) = v0;
            *reinterpret_cast<float2*>(&out[(size_t)(m + 8) * N_DIM + n]) = v1;
        }
    }
}

extern "C" void kernel_launch(void* const* d_in, const int* in_sizes, int n_in,
                              void* d_out, int out_size) {
    const float* x       = (const float*)d_in[0];
    const int*   qweight = (const int*)d_in[1];
    const float* scales  = (const float*)d_in[2];
    const int*   qzeros  = (const int*)d_in[3];
    // d_in[4] = g_idx: k/128, folded into dequant indexing
    const float* bias    = (const float*)d_in[5];
    float* out = (float*)d_out;

    convert_x_kernel<<<((size_t)M_DIM * K_DIM) / (256 * 8), 256>>>(x);
    dequant_kernel<<<512, 256>>>(qweight, scales, qzeros);

    dim3 grid(N_DIM / BN, M_DIM / BM);
    gemm_kernel<<<grid, 256>>>(bias, out);
}

// round 15
// speedup vs baseline: 1.1308x; 1.0940x over previous
#include <cuda_runtime.h>
#include <cuda_fp16.h>
#include <cstdint>

#define K_DIM 4096
#define N_DIM 4096
#define M_DIM 8192

#define BM 128
#define BN 128
#define BK 32
#define PADH 8
#define NTILES (K_DIM / BK)

#define CONV_BLOCKS 16384   // blocks doing x conversion (256 thr * 8 floats)
#define DEQ_BLOCKS 512      // blocks doing dequant

// Dequantized weights [N][K], K contiguous, k PERMUTED within 8-blocks
// (order 0,4,1,5,2,6,3,7). g_X uses the same permutation -> dot products equal.
__device__ __half g_W[(size_t)N_DIM * K_DIM];
__device__ __half g_X[(size_t)M_DIM * K_DIM];

// ---------------- Kernel 0+1 merged: prep (convert x || dequant W) ----------------
// Blocks [0, CONV_BLOCKS): fp32 -> fp16 conversion of x, k-permuted in 8-blocks.
// Blocks [CONV_BLOCKS, CONV_BLOCKS+DEQ_BLOCKS): GPTQ 4-bit dequant (LOP3 magic).
// The two halves touch disjoint data; merging lets them overlap on HBM.
__global__ __launch_bounds__(256) void prep_kernel(const float* __restrict__ xf,
                                                   const int* __restrict__ qw,
                                                   const float* __restrict__ scales,
                                                   const int* __restrict__ qz) {
    if (blockIdx.x < CONV_BLOCKS) {
        size_t i = ((size_t)blockIdx.x * blockDim.x + threadIdx.x) * 8;
        float4 v0 = *reinterpret_cast<const float4*>(xf + i);
        float4 v1 = *reinterpret_cast<const float4*>(xf + i + 4);
        __half h[8];
        // permuted order: x0,x4,x1,x5,x2,x6,x3,x7
        h[0] = __float2half_rn(v0.x); h[1] = __float2half_rn(v1.x);
        h[2] = __float2half_rn(v0.y); h[3] = __float2half_rn(v1.y);
        h[4] = __float2half_rn(v0.z); h[5] = __float2half_rn(v1.z);
        h[6] = __float2half_rn(v0.w); h[7] = __float2half_rn(v1.w);
        *reinterpret_cast<uint4*>(&g_X[i]) = *reinterpret_cast<const uint4*>(h);
    } else {
        // warp owns 32 consecutive n and one group g (16 qweight rows).
        // t = ((w>>4j)&0x000F000F)|0x64006400 -> half2 (1024+v_j, 1024+v_{j+4});
        // hsub2 of (1024+z) exact; hmul2 by fp16 scale = reference rounding.
        int gw = (blockIdx.x - CONV_BLOCKS) * 8 + (threadIdx.x >> 5);  // 0..4095
        int lane = threadIdx.x & 31;
        int n = (gw & 127) * 32 + lane;
        int g = gw >> 7;                                // 0..31
        __half s = __float2half_rn(scales[g * N_DIM + n]);
        __half2 s2 = __half2half2(s);
        int z = ((qz[g * (N_DIM / 8) + (n >> 3)] >> ((n & 7) * 4)) & 0xF) + 1;
        __half2 mz = __half2half2(__float2half_rn(1024.0f + (float)z));
        const int r0 = g * 16;
#pragma unroll
        for (int i = 0; i < 16; i++) {
            int w = qw[(size_t)(r0 + i) * N_DIM + n];
            uint32_t outv[4];
#pragma unroll
            for (int j = 0; j < 4; j++) {
                uint32_t t = (((uint32_t)w >> (4 * j)) & 0x000F000Fu) | 0x64006400u;
                __half2 hv = __hmul2(__hsub2(*reinterpret_cast<__half2*>(&t), mz), s2);
                outv[j] = *reinterpret_cast<uint32_t*>(&hv);
            }
            *reinterpret_cast<uint4*>(&g_W[(size_t)n * K_DIM + (r0 + i) * 8]) =
                *reinterpret_cast<const uint4*>(outv);
        }
    }
}

// ---------------- Kernel 2: GEMM (verbatim R2 config: measured best) ----------------
// out[m][n] = fp16round(sum) + fp16(bias); 128x128x32 CTA tile, 8 warps 2(M)x4(N),
// warp tile 64x32. 2-stage cp.async; ldmatrix from padded smem; natural regs.
__global__ __launch_bounds__(256) void gemm_kernel(const float* __restrict__ biasf,
                                                   float* __restrict__ out) {
    __shared__ __half As[2][BM][BK + PADH];
    __shared__ __half Bs[2][BN][BK + PADH];

    const int tid = threadIdx.x;
    const int lane = tid & 31;
    const int warp = tid >> 5;
    const int warpM = warp & 1;   // 0..1
    const int warpN = warp >> 1;  // 0..3
    const int bm = blockIdx.y * BM;
    const int bn = blockIdx.x * BN;

    float c[4][4][4];
#pragma unroll
    for (int i = 0; i < 4; i++)
#pragma unroll
        for (int j = 0; j < 4; j++)
#pragma unroll
            for (int e = 0; e < 4; e++) c[i][j][e] = 0.0f;

    auto load_stage = [&](int s, int kt) {
#pragma unroll
        for (int i = 0; i < 2; i++) {
            int id = tid + i * 256;      // 512 16B vectors per operand per stage
            int row = id >> 2;           // 0..127
            int c8 = (id & 3) * 8;       // 0,8,16,24 halves
            const __half* srcA = g_X + (size_t)(bm + row) * K_DIM + kt * BK + c8;
            uint32_t dA = (uint32_t)__cvta_generic_to_shared(&As[s][row][c8]);
            asm volatile("cp.async.cg.shared.global [%0], [%1], 16;" :: "r"(dA), "l"(srcA));
            const __half* srcB = g_W + (size_t)(bn + row) * K_DIM + kt * BK + c8;
            uint32_t dB = (uint32_t)__cvta_generic_to_shared(&Bs[s][row][c8]);
            asm volatile("cp.async.cg.shared.global [%0], [%1], 16;" :: "r"(dB), "l"(srcB));
        }
        asm volatile("cp.async.commit_group;");
    };

    load_stage(0, 0);
    int cur = 0;

    for (int kt = 0; kt < NTILES; kt++) {
        asm volatile("cp.async.wait_group 0;");
        __syncthreads();
        if (kt + 1 < NTILES) load_stage(cur ^ 1, kt + 1);

#pragma unroll
        for (int kk = 0; kk < BK; kk += 16) {
            uint32_t a[4][4];
#pragma unroll
            for (int fm = 0; fm < 4; fm++) {
                int m0 = warpM * 64 + fm * 16 + (lane & 15);
                uint32_t addr = (uint32_t)__cvta_generic_to_shared(
                    &As[cur][m0][kk + ((lane >> 4) << 3)]);
                asm volatile("ldmatrix.sync.aligned.m8n8.x4.shared.b16 {%0,%1,%2,%3}, [%4];"
                             : "=r"(a[fm][0]), "=r"(a[fm][1]), "=r"(a[fm][2]), "=r"(a[fm][3])
                             : "r"(addr));
            }
            uint32_t b[4][2];
#pragma unroll
            for (int fn = 0; fn < 4; fn++) {
                int n0 = warpN * 32 + fn * 8 + (lane & 7);
                uint32_t addr = (uint32_t)__cvta_generic_to_shared(
                    &Bs[cur][n0][kk + ((lane >> 3) & 1) * 8]);
                asm volatile("ldmatrix.sync.aligned.m8n8.x2.shared.b16 {%0,%1}, [%2];"
                             : "=r"(b[fn][0]), "=r"(b[fn][1])
                             : "r"(addr));
            }
#pragma unroll
            for (int fm = 0; fm < 4; fm++)
#pragma unroll
                for (int fn = 0; fn < 4; fn++) {
                    asm volatile(
                        "mma.sync.aligned.m16n8k16.row.col.f32.f16.f16.f32 "
                        "{%0,%1,%2,%3}, {%4,%5,%6,%7}, {%8,%9}, {%0,%1,%2,%3};"
                        : "+f"(c[fm][fn][0]), "+f"(c[fm][fn][1]),
                          "+f"(c[fm][fn][2]), "+f"(c[fm][fn][3])
                        : "r"(a[fm][0]), "r"(a[fm][1]), "r"(a[fm][2]), "r"(a[fm][3]),
                          "r"(b[fn][0]), "r"(b[fn][1]));
                }
        }
        cur ^= 1;
    }

    // Epilogue: fp16(sum) + fp16(bias) in fp16, store f32 (reference rounding).
    const int row_in = lane >> 2;         // 0..7
    const int col_in = (lane & 3) * 2;    // 0,2,4,6
#pragma unroll
    for (int fn = 0; fn < 4; fn++) {
        int n = bn + warpN * 32 + fn * 8 + col_in;
        __half bh0 = __float2half_rn(biasf[n]);
        __half bh1 = __float2half_rn(biasf[n + 1]);
#pragma unroll
        for (int fm = 0; fm < 4; fm++) {
            int m = bm + warpM * 64 + fm * 16 + row_in;
            float2 v0, v1;
            v0.x = __half2float(__hadd(__float2half_rn(c[fm][fn][0]), bh0));
            v0.y = __half2float(__hadd(__float2half_rn(c[fm][fn][1]), bh1));
            v1.x = __half2float(__hadd(__float2half_rn(c[fm][fn][2]), bh0));
            v1.y = __half2float(__hadd(__float2half_rn(c[fm][fn][3]), bh1));
            *reinterpret_cast<float2*>(&out[(size_t)m * N_DIM + n]) = v0;
            *reinterpret_cast<float2*>(&out[(size_t)(m + 8) * N_DIM + n]) = v1;
        }
    }
}

extern "C" void kernel_launch(void* const* d_in, const int* in_sizes, int n_in,
                              void* d_out, int out_size) {
    const float* x       = (const float*)d_in[0];
    const int*   qweight = (const int*)d_in[1];
    const float* scales  = (const float*)d_in[2];
    const int*   qzeros  = (const int*)d_in[3];
    // d_in[4] = g_idx: k/128, folded into dequant indexing
    const float* bias    = (const float*)d_in[5];
    float* out = (float*)d_out;

    prep_kernel<<<CONV_BLOCKS + DEQ_BLOCKS, 256>>>(x, qweight, scales, qzeros);

    dim3 grid(N_DIM / BN, M_DIM / BM);
    gemm_kernel<<<grid, 256>>>(bias, out);
}